// round 3
// baseline (speedup 1.0000x reference)
#include <cuda_runtime.h>
#include <cstddef>

#define Nn 50000
#define Ee 800000
#define Rr 8
#define Bb 4
#define Hh 128

// ---- device scratch (no allocations allowed; referenced directly from device code) ----
__device__ float g_S[(size_t)Nn * Rr * Hh];   // 204.8 MB raw per-(dst,rel) sums
__device__ float g_T[(size_t)Nn * Bb * Hh];   // 102.4 MB basis-compressed sums
__device__ float g_cnt[Nn * Rr];              // per-(dst,rel) edge counts
__device__ float g_xr[(size_t)Nn * Hh];       // post-BN+ReLU activations
__device__ float g_W[Hh * Hh];                // root + skip combined weight
__device__ float g_bias[Hh];                  // bias + skip_b combined
__device__ float g_stat[2 * Hh];              // BN: sum, sumsq
__device__ float g_bnA[Hh], g_bnB[Hh];        // BN affine

// ---- zero kernels (no host pointers to device symbols needed) ----
__global__ void k_zero_S() {
    size_t i = (size_t)blockIdx.x * blockDim.x + threadIdx.x;
    if (i < (size_t)Nn * Rr * Hh / 4)
        ((float4*)g_S)[i] = make_float4(0.f, 0.f, 0.f, 0.f);
}
__global__ void k_zero_cnt() {
    int i = blockIdx.x * blockDim.x + threadIdx.x;
    if (i < Nn * Rr) g_cnt[i] = 0.f;
}
__global__ void k_zero_stat() {
    int i = threadIdx.x;
    if (i < 2 * Hh) g_stat[i] = 0.f;
}

// ---- per-(dst,relation) in-degree counts ----
__global__ void k_count(const int* __restrict__ ei, const int* __restrict__ et) {
    int e = blockIdx.x * blockDim.x + threadIdx.x;
    if (e < Ee) {
        int d = ei[Ee + e];
        int r = et[e];
        atomicAdd(&g_cnt[d * Rr + r], 1.0f);
    }
}

// ---- scatter: S[dst,rel,:] += x[src,:]  (one warp per edge, vector red) ----
template <bool FROM_XR>
__global__ void k_scatter(const int* __restrict__ ei, const int* __restrict__ et,
                          const float* __restrict__ X) {
    int gtid = blockIdx.x * blockDim.x + threadIdx.x;
    int w = gtid >> 5;
    int lane = threadIdx.x & 31;
    if (w >= Ee) return;
    int s = ei[w];
    int d = ei[Ee + w];
    int r = et[w];
    const float4* src4 = FROM_XR ? (const float4*)g_xr : (const float4*)X;
    float4 v = src4[(size_t)s * 32 + lane];
    float* dst = &g_S[((size_t)(d * Rr + r)) * Hh + lane * 4];
    asm volatile("red.global.add.v4.f32 [%0], {%1,%2,%3,%4};"
                 :: "l"(dst), "f"(v.x), "f"(v.y), "f"(v.z), "f"(v.w) : "memory");
}

// ---- compress: T[n,b,:] = sum_r comp[r,b] * (1/max(cnt,1)) * S[n,r,:] ----
__global__ void k_compress(const float* __restrict__ comp) {
    int n = blockIdx.x;
    int c = threadIdx.x;
    __shared__ float inv[Rr];
    __shared__ float cm[Rr * Bb];
    if (c < Rr) {
        float cc = g_cnt[n * Rr + c];
        inv[c] = 1.0f / fmaxf(cc, 1.0f);
    }
    if (c < Rr * Bb) cm[c] = comp[c];
    __syncthreads();
    const float* row = &g_S[(size_t)n * (Rr * Hh)];
    float s[Rr];
#pragma unroll
    for (int r = 0; r < Rr; r++) s[r] = row[r * Hh + c] * inv[r];
    float* trow = &g_T[(size_t)n * (Bb * Hh)];
#pragma unroll
    for (int b = 0; b < Bb; b++) {
        float t = 0.f;
#pragma unroll
        for (int r = 0; r < Rr; r++) t += cm[r * Bb + b] * s[r];
        trow[b * Hh + c] = t;
    }
}

// ---- prep: W = root + skip_w ; bias = bias + skip_b ----
__global__ void k_prep(const float* __restrict__ root, const float* __restrict__ skw,
                       const float* __restrict__ bias, const float* __restrict__ skb) {
    int i = blockIdx.x * blockDim.x + threadIdx.x;
    if (i < Hh * Hh) g_W[i] = root[i] + skw[i];
    if (i < Hh) g_bias[i] = bias[i] + skb[i];
}

// ---- SGEMM: C[M,128] = [T | Asec] @ [bases ; W] + bias
//      M=50000, K=640 (512 basis + 128 root/skip), N=128
//      64x128 block tile, 256 threads, 8 rows x 4 cols per thread ----
template <bool FROM_XR>
__global__ void __launch_bounds__(256)
k_gemm(const float* __restrict__ Asec, const float* __restrict__ B1,
       float* __restrict__ C) {
    __shared__ float As[32 * 68];      // k-major, padded stride 68 (16B aligned per k-row)
    __shared__ float Bs[32 * 128];
    int tid = threadIdx.x;
    int r0 = (tid >> 5) * 8;           // row group within 64 (per-warp uniform)
    int cg = tid & 31;                 // col group (4 floats)
    int m0 = blockIdx.x * 64;
    float acc[8][4] = {};

    const float4* xsec4 = FROM_XR ? (const float4*)g_xr : (const float4*)Asec;

    for (int kc = 0; kc < 20; kc++) {
        int kk = kc * 32;
        // load A tile (64 rows x 32 k), transpose into smem
#pragma unroll
        for (int t = 0; t < 2; t++) {
            int idx = tid + t * 256;
            int row = idx >> 3, kq = idx & 7;
            int n = m0 + row;
            float4 v = make_float4(0.f, 0.f, 0.f, 0.f);
            if (n < Nn) {
                if (kc < 16) v = *(const float4*)&g_T[(size_t)n * 512 + kk + kq * 4];
                else         v = xsec4[(size_t)n * 32 + ((kk - 512) >> 2) + kq];
            }
            int kb = kq * 4;
            As[(kb + 0) * 68 + row] = v.x;
            As[(kb + 1) * 68 + row] = v.y;
            As[(kb + 2) * 68 + row] = v.z;
            As[(kb + 3) * 68 + row] = v.w;
        }
        // load B tile (32 k x 128 f)
#pragma unroll
        for (int t = 0; t < 4; t++) {
            int idx = tid + t * 256;
            int kr = idx >> 5, fq = idx & 31;
            const float* Bsrc = (kc < 16) ? &B1[(size_t)(kk + kr) * 128]
                                          : &g_W[(size_t)(kk - 512 + kr) * 128];
            ((float4*)Bs)[kr * 32 + fq] = ((const float4*)Bsrc)[fq];
        }
        __syncthreads();
#pragma unroll
        for (int k = 0; k < 32; k++) {
            float4 b = ((float4*)Bs)[k * 32 + cg];
            // A row-group loads: warp-uniform address -> broadcast, vectorized
            float4 a01 = *(const float4*)&As[k * 68 + r0];
            float4 a23 = *(const float4*)&As[k * 68 + r0 + 4];
            float a0[8] = {a01.x, a01.y, a01.z, a01.w, a23.x, a23.y, a23.z, a23.w};
#pragma unroll
            for (int j = 0; j < 8; j++) {
                acc[j][0] += a0[j] * b.x;
                acc[j][1] += a0[j] * b.y;
                acc[j][2] += a0[j] * b.z;
                acc[j][3] += a0[j] * b.w;
            }
        }
        __syncthreads();
    }
    float4 bv = *(const float4*)&g_bias[cg * 4];
#pragma unroll
    for (int j = 0; j < 8; j++) {
        int n = m0 + r0 + j;
        if (n < Nn) {
            float4 o = make_float4(acc[j][0] + bv.x, acc[j][1] + bv.y,
                                   acc[j][2] + bv.z, acc[j][3] + bv.w);
            *(float4*)&C[(size_t)n * 128 + cg * 4] = o;
        }
    }
}

// ---- BatchNorm stats (per-channel sum / sumsq) ----
#define BN_ROWS 256
__global__ void k_bnstats(const float* __restrict__ X) {
    int c = threadIdx.x;
    int n0 = blockIdx.x * BN_ROWS;
    float s = 0.f, s2 = 0.f;
    for (int i = 0; i < BN_ROWS; i++) {
        int n = n0 + i;
        if (n < Nn) {
            float v = X[(size_t)n * Hh + c];
            s += v;
            s2 += v * v;
        }
    }
    atomicAdd(&g_stat[c], s);
    atomicAdd(&g_stat[Hh + c], s2);
}

__global__ void k_bnfin(const float* __restrict__ gamma, const float* __restrict__ beta) {
    int c = threadIdx.x;
    float m = g_stat[c] * (1.0f / Nn);
    float var = g_stat[Hh + c] * (1.0f / Nn) - m * m;
    float a = gamma[c] * rsqrtf(var + 1e-5f);
    g_bnA[c] = a;
    g_bnB[c] = beta[c] - m * a;
}

__global__ void k_bnapply(const float* __restrict__ X) {
    size_t i = (size_t)blockIdx.x * blockDim.x + threadIdx.x;  // over Nn*32 float4
    if (i >= (size_t)Nn * 32) return;
    int cq = ((int)(i & 31)) * 4;
    float4 v = ((const float4*)X)[i];
    float4 a = *(const float4*)&g_bnA[cq];
    float4 b = *(const float4*)&g_bnB[cq];
    v.x = fmaxf(a.x * v.x + b.x, 0.f);
    v.y = fmaxf(a.y * v.y + b.y, 0.f);
    v.z = fmaxf(a.z * v.z + b.z, 0.f);
    v.w = fmaxf(a.w * v.w + b.w, 0.f);
    ((float4*)g_xr)[i] = v;
}

extern "C" void kernel_launch(void* const* d_in, const int* in_sizes, int n_in,
                              void* d_out, int out_size) {
    const float* x       = (const float*)d_in[0];
    const int*   ei      = (const int*)d_in[1];
    const int*   et      = (const int*)d_in[2];
    const float* comp1   = (const float*)d_in[3];
    const float* bases1  = (const float*)d_in[4];
    const float* root1   = (const float*)d_in[5];
    const float* bias1   = (const float*)d_in[6];
    const float* skip1_w = (const float*)d_in[7];
    const float* skip1_b = (const float*)d_in[8];
    const float* gamma   = (const float*)d_in[9];
    const float* beta    = (const float*)d_in[10];
    const float* comp2   = (const float*)d_in[11];
    const float* bases2  = (const float*)d_in[12];
    const float* root2   = (const float*)d_in[13];
    const float* bias2   = (const float*)d_in[14];
    const float* skip2_w = (const float*)d_in[15];
    const float* skip2_b = (const float*)d_in[16];

    float* out_h  = (float*)d_out;                       // [N,128] pre-BN x1
    float* out_x2 = (float*)d_out + (size_t)Nn * Hh;     // [N,128] final

    const unsigned ZS = (unsigned)(((size_t)Nn * Rr * Hh / 4 + 255) / 256);

    // counts (shared between layers)
    k_zero_cnt<<<(Nn * Rr + 255) / 256, 256>>>();
    k_count<<<(Ee + 255) / 256, 256>>>(ei, et);

    // ---- layer 1 ----
    k_zero_S<<<ZS, 256>>>();
    k_scatter<false><<<(Ee * 32 + 255) / 256, 256>>>(ei, et, x);
    k_prep<<<64, 256>>>(root1, skip1_w, bias1, skip1_b);
    k_compress<<<Nn, 128>>>(comp1);
    k_gemm<false><<<(Nn + 63) / 64, 256>>>(x, bases1, out_h);

    // ---- BatchNorm + ReLU ----
    k_zero_stat<<<1, 256>>>();
    k_bnstats<<<(Nn + BN_ROWS - 1) / BN_ROWS, 128>>>(out_h);
    k_bnfin<<<1, 128>>>(gamma, beta);
    k_bnapply<<<(unsigned)(((size_t)Nn * 32 + 255) / 256), 256>>>(out_h);

    // ---- layer 2 ----
    k_zero_S<<<ZS, 256>>>();
    k_scatter<true><<<(Ee * 32 + 255) / 256, 256>>>(ei, et, nullptr);
    k_prep<<<64, 256>>>(root2, skip2_w, bias2, skip2_b);
    k_compress<<<Nn, 128>>>(comp2);
    k_gemm<true><<<(Nn + 63) / 64, 256>>>(nullptr, bases2, out_x2);
}

// round 4
// speedup vs baseline: 1.3321x; 1.3321x over previous
#include <cuda_runtime.h>
#include <cstddef>

#define Nn 50000
#define Ee 800000
#define Rr 8
#define Bb 4
#define Hh 128

// ---- device scratch (no allocations allowed) ----
__device__ float g_T[(size_t)Nn * Bb * Hh];   // 102.4 MB basis-compressed aggregates
__device__ float g_cnt[Nn * Rr];              // per-(dst,rel) edge counts
__device__ float g_xr[(size_t)Nn * Hh];       // post-BN+ReLU activations
__device__ float g_W[Hh * Hh];                // root + skip combined weight
__device__ float g_bias[Hh];                  // bias + skip_b combined
__device__ float g_stat[2 * Hh];              // BN: sum, sumsq
__device__ float g_bnA[Hh], g_bnB[Hh];        // BN affine
// CSR by destination
__device__ int g_off[Nn + 1];
__device__ int g_cur[Nn];
__device__ int g_epk[Ee];                     // packed src | (rel<<24)
__device__ int g_bsum[64];

// ---- zero helpers ----
__global__ void k_zero_cnt() {
    int i = blockIdx.x * blockDim.x + threadIdx.x;
    if (i < Nn * Rr) g_cnt[i] = 0.f;
}
__global__ void k_zero_stat() {
    int i = threadIdx.x;
    if (i < 2 * Hh) g_stat[i] = 0.f;
}

// ---- per-(dst,relation) in-degree counts ----
__global__ void k_count(const int* __restrict__ ei, const int* __restrict__ et) {
    int e = blockIdx.x * blockDim.x + threadIdx.x;
    if (e < Ee) {
        int d = ei[Ee + e];
        int r = et[e];
        atomicAdd(&g_cnt[d * Rr + r], 1.0f);
    }
}

// ---- CSR build: per-node degree from cnt, 2-level exclusive scan ----
__global__ void __launch_bounds__(256) k_scan1() {
    __shared__ int sh[256];
    int tid = threadIdx.x;
    int base = blockIdx.x * 1024;
    int d[4];
    int local = 0;
#pragma unroll
    for (int j = 0; j < 4; j++) {
        int n = base + tid * 4 + j;
        int deg = 0;
        if (n < Nn) {
#pragma unroll
            for (int r = 0; r < Rr; r++) deg += (int)g_cnt[n * Rr + r];
        }
        d[j] = deg;
        local += deg;
    }
    sh[tid] = local;
    __syncthreads();
    for (int s = 1; s < 256; s <<= 1) {
        int v = (tid >= s) ? sh[tid - s] : 0;
        __syncthreads();
        sh[tid] += v;
        __syncthreads();
    }
    int run = sh[tid] - local;  // exclusive
    if (tid == 255) g_bsum[blockIdx.x] = sh[255];
#pragma unroll
    for (int j = 0; j < 4; j++) {
        int n = base + tid * 4 + j;
        if (n < Nn) g_off[n] = run;
        run += d[j];
    }
}

__global__ void k_scan2() {
    __shared__ int sh[64];
    int tid = threadIdx.x;
    int v = (tid < 49) ? g_bsum[tid] : 0;
    sh[tid] = v;
    __syncthreads();
    for (int s = 1; s < 64; s <<= 1) {
        int u = (tid >= s) ? sh[tid - s] : 0;
        __syncthreads();
        sh[tid] += u;
        __syncthreads();
    }
    if (tid < 49) g_bsum[tid] = sh[tid] - v;  // exclusive
    if (tid == 0) g_off[Nn] = Ee;
}

__global__ void k_scan3() {
    int n = blockIdx.x * blockDim.x + threadIdx.x;
    if (n < Nn) {
        int o = g_off[n] + g_bsum[n >> 10];
        g_off[n] = o;
        g_cur[n] = o;
    }
}

__global__ void k_place(const int* __restrict__ ei, const int* __restrict__ et) {
    int e = blockIdx.x * blockDim.x + threadIdx.x;
    if (e < Ee) {
        int d = ei[Ee + e];
        int s = ei[e];
        int r = et[e];
        int pos = atomicAdd(&g_cur[d], 1);
        g_epk[pos] = s | (r << 24);
    }
}

// ---- gather-aggregate: T[n,b,:] = sum_{e->n} coef[rel_e,b] * x[src_e,:]
//      coef[r,b] = comp[r,b] / max(cnt[n,r],1). One block per node. ----
template <bool FROM_XR>
__global__ void __launch_bounds__(128) k_agg(const float* __restrict__ X,
                                             const float* __restrict__ comp) {
    int n = blockIdx.x;
    int c = threadIdx.x;
    __shared__ float coef[Rr * 4];   // [r][b]
    __shared__ int se[32];
    if (c < Rr * Bb) {
        int r = c >> 2, b = c & 3;
        float cc = g_cnt[n * Rr + r];
        coef[r * 4 + b] = comp[r * Bb + b] / fmaxf(cc, 1.0f);
    }
    int start = g_off[n], end = g_off[n + 1];
    __syncthreads();
    const float* Xp = FROM_XR ? g_xr : X;
    float a0 = 0.f, a1 = 0.f, a2 = 0.f, a3 = 0.f;
    for (int base = start; base < end; base += 32) {
        int m = min(32, end - base);
        if (c < m) se[c] = g_epk[base + c];
        __syncthreads();
        int i = 0;
        for (; i + 1 < m; i += 2) {
            int pk0 = se[i], pk1 = se[i + 1];
            int s0 = pk0 & 0xFFFFFF, r0 = pk0 >> 24;
            int s1 = pk1 & 0xFFFFFF, r1 = pk1 >> 24;
            float xv0 = Xp[(size_t)s0 * Hh + c];
            float xv1 = Xp[(size_t)s1 * Hh + c];
            a0 += coef[r0 * 4 + 0] * xv0; a1 += coef[r0 * 4 + 1] * xv0;
            a2 += coef[r0 * 4 + 2] * xv0; a3 += coef[r0 * 4 + 3] * xv0;
            a0 += coef[r1 * 4 + 0] * xv1; a1 += coef[r1 * 4 + 1] * xv1;
            a2 += coef[r1 * 4 + 2] * xv1; a3 += coef[r1 * 4 + 3] * xv1;
        }
        if (i < m) {
            int pk = se[i];
            int s = pk & 0xFFFFFF, r = pk >> 24;
            float xv = Xp[(size_t)s * Hh + c];
            a0 += coef[r * 4 + 0] * xv; a1 += coef[r * 4 + 1] * xv;
            a2 += coef[r * 4 + 2] * xv; a3 += coef[r * 4 + 3] * xv;
        }
        __syncthreads();
    }
    size_t t = (size_t)n * 512 + c;
    g_T[t] = a0; g_T[t + 128] = a1; g_T[t + 256] = a2; g_T[t + 384] = a3;
}

// ---- prep: W = root + skip_w ; bias = bias + skip_b ----
__global__ void k_prep(const float* __restrict__ root, const float* __restrict__ skw,
                       const float* __restrict__ bias, const float* __restrict__ skb) {
    int i = blockIdx.x * blockDim.x + threadIdx.x;
    if (i < Hh * Hh) g_W[i] = root[i] + skw[i];
    if (i < Hh) g_bias[i] = bias[i] + skb[i];
}

// ---- SGEMM: C[M,128] = [T | Asec] @ [bases ; W] + bias
//      M=50000, K=640, N=128; 64x128 tile, 256 threads, 8x4/thread ----
template <bool FROM_XR>
__global__ void __launch_bounds__(256)
k_gemm(const float* __restrict__ Asec, const float* __restrict__ B1,
       float* __restrict__ C) {
    __shared__ float As[32 * 68];
    __shared__ float Bs[32 * 128];
    int tid = threadIdx.x;
    int r0 = (tid >> 5) * 8;
    int cg = tid & 31;
    int m0 = blockIdx.x * 64;
    float acc[8][4] = {};

    const float4* xsec4 = FROM_XR ? (const float4*)g_xr : (const float4*)Asec;

    for (int kc = 0; kc < 20; kc++) {
        int kk = kc * 32;
#pragma unroll
        for (int t = 0; t < 2; t++) {
            int idx = tid + t * 256;
            int row = idx >> 3, kq = idx & 7;
            int n = m0 + row;
            float4 v = make_float4(0.f, 0.f, 0.f, 0.f);
            if (n < Nn) {
                if (kc < 16) v = *(const float4*)&g_T[(size_t)n * 512 + kk + kq * 4];
                else         v = xsec4[(size_t)n * 32 + ((kk - 512) >> 2) + kq];
            }
            int kb = kq * 4;
            As[(kb + 0) * 68 + row] = v.x;
            As[(kb + 1) * 68 + row] = v.y;
            As[(kb + 2) * 68 + row] = v.z;
            As[(kb + 3) * 68 + row] = v.w;
        }
#pragma unroll
        for (int t = 0; t < 4; t++) {
            int idx = tid + t * 256;
            int kr = idx >> 5, fq = idx & 31;
            const float* Bsrc = (kc < 16) ? &B1[(size_t)(kk + kr) * 128]
                                          : &g_W[(size_t)(kk - 512 + kr) * 128];
            ((float4*)Bs)[kr * 32 + fq] = ((const float4*)Bsrc)[fq];
        }
        __syncthreads();
#pragma unroll
        for (int k = 0; k < 32; k++) {
            float4 b = ((float4*)Bs)[k * 32 + cg];
            float4 a01 = *(const float4*)&As[k * 68 + r0];
            float4 a23 = *(const float4*)&As[k * 68 + r0 + 4];
            float a0[8] = {a01.x, a01.y, a01.z, a01.w, a23.x, a23.y, a23.z, a23.w};
#pragma unroll
            for (int j = 0; j < 8; j++) {
                acc[j][0] += a0[j] * b.x;
                acc[j][1] += a0[j] * b.y;
                acc[j][2] += a0[j] * b.z;
                acc[j][3] += a0[j] * b.w;
            }
        }
        __syncthreads();
    }
    float4 bv = *(const float4*)&g_bias[cg * 4];
#pragma unroll
    for (int j = 0; j < 8; j++) {
        int n = m0 + r0 + j;
        if (n < Nn) {
            float4 o = make_float4(acc[j][0] + bv.x, acc[j][1] + bv.y,
                                   acc[j][2] + bv.z, acc[j][3] + bv.w);
            *(float4*)&C[(size_t)n * 128 + cg * 4] = o;
        }
    }
}

// ---- BatchNorm ----
#define BN_ROWS 256
__global__ void k_bnstats(const float* __restrict__ X) {
    int c = threadIdx.x;
    int n0 = blockIdx.x * BN_ROWS;
    float s = 0.f, s2 = 0.f;
    for (int i = 0; i < BN_ROWS; i++) {
        int n = n0 + i;
        if (n < Nn) {
            float v = X[(size_t)n * Hh + c];
            s += v;
            s2 += v * v;
        }
    }
    atomicAdd(&g_stat[c], s);
    atomicAdd(&g_stat[Hh + c], s2);
}

__global__ void k_bnfin(const float* __restrict__ gamma, const float* __restrict__ beta) {
    int c = threadIdx.x;
    float m = g_stat[c] * (1.0f / Nn);
    float var = g_stat[Hh + c] * (1.0f / Nn) - m * m;
    float a = gamma[c] * rsqrtf(var + 1e-5f);
    g_bnA[c] = a;
    g_bnB[c] = beta[c] - m * a;
}

__global__ void k_bnapply(const float* __restrict__ X) {
    size_t i = (size_t)blockIdx.x * blockDim.x + threadIdx.x;
    if (i >= (size_t)Nn * 32) return;
    int cq = ((int)(i & 31)) * 4;
    float4 v = ((const float4*)X)[i];
    float4 a = *(const float4*)&g_bnA[cq];
    float4 b = *(const float4*)&g_bnB[cq];
    v.x = fmaxf(a.x * v.x + b.x, 0.f);
    v.y = fmaxf(a.y * v.y + b.y, 0.f);
    v.z = fmaxf(a.z * v.z + b.z, 0.f);
    v.w = fmaxf(a.w * v.w + b.w, 0.f);
    ((float4*)g_xr)[i] = v;
}

extern "C" void kernel_launch(void* const* d_in, const int* in_sizes, int n_in,
                              void* d_out, int out_size) {
    const float* x       = (const float*)d_in[0];
    const int*   ei      = (const int*)d_in[1];
    const int*   et      = (const int*)d_in[2];
    const float* comp1   = (const float*)d_in[3];
    const float* bases1  = (const float*)d_in[4];
    const float* root1   = (const float*)d_in[5];
    const float* bias1   = (const float*)d_in[6];
    const float* skip1_w = (const float*)d_in[7];
    const float* skip1_b = (const float*)d_in[8];
    const float* gamma   = (const float*)d_in[9];
    const float* beta    = (const float*)d_in[10];
    const float* comp2   = (const float*)d_in[11];
    const float* bases2  = (const float*)d_in[12];
    const float* root2   = (const float*)d_in[13];
    const float* bias2   = (const float*)d_in[14];
    const float* skip2_w = (const float*)d_in[15];
    const float* skip2_b = (const float*)d_in[16];

    float* out_h  = (float*)d_out;
    float* out_x2 = (float*)d_out + (size_t)Nn * Hh;

    // ---- CSR build (shared between layers) ----
    k_zero_cnt<<<(Nn * Rr + 255) / 256, 256>>>();
    k_count<<<(Ee + 255) / 256, 256>>>(ei, et);
    k_scan1<<<(Nn + 1023) / 1024, 256>>>();
    k_scan2<<<1, 64>>>();
    k_scan3<<<(Nn + 255) / 256, 256>>>();
    k_place<<<(Ee + 255) / 256, 256>>>(ei, et);

    // ---- layer 1 ----
    k_prep<<<64, 256>>>(root1, skip1_w, bias1, skip1_b);
    k_agg<false><<<Nn, 128>>>(x, comp1);
    k_gemm<false><<<(Nn + 63) / 64, 256>>>(x, bases1, out_h);

    // ---- BatchNorm + ReLU ----
    k_zero_stat<<<1, 256>>>();
    k_bnstats<<<(Nn + BN_ROWS - 1) / BN_ROWS, 128>>>(out_h);
    k_bnfin<<<1, 128>>>(gamma, beta);
    k_bnapply<<<(unsigned)(((size_t)Nn * 32 + 255) / 256), 256>>>(out_h);

    // ---- layer 2 ----
    k_prep<<<64, 256>>>(root2, skip2_w, bias2, skip2_b);
    k_agg<true><<<Nn, 128>>>(nullptr, comp2);
    k_gemm<true><<<(Nn + 63) / 64, 256>>>(nullptr, bases2, out_x2);
}

// round 6
// speedup vs baseline: 1.4230x; 1.0683x over previous
#include <cuda_runtime.h>
#include <cstddef>

#define Nn 50000
#define Ee 800000
#define Rr 8
#define Bb 4
#define Hh 128

typedef unsigned long long u64;

// ---- packed f32x2 helpers (sm_103a FFMA2 — only reachable via PTX) ----
__device__ __forceinline__ u64 pack2(float v) {
    u64 r;
    asm("mov.b64 %0, {%1, %1};" : "=l"(r) : "f"(v));
    return r;
}
__device__ __forceinline__ u64 fma2(u64 a, u64 b, u64 c) {
    u64 d;
    asm("fma.rn.f32x2 %0, %1, %2, %3;" : "=l"(d) : "l"(a), "l"(b), "l"(c));
    return d;
}
__device__ __forceinline__ float lo2(u64 v) { return __uint_as_float((unsigned)v); }
__device__ __forceinline__ float hi2(u64 v) { return __uint_as_float((unsigned)(v >> 32)); }

// ---- device scratch ----
__device__ float g_T[(size_t)Nn * Bb * Hh];   // basis-compressed aggregates
__device__ float g_cnt[Nn * Rr];
__device__ float g_xr[(size_t)Nn * Hh];
__device__ float g_W[Hh * Hh];
__device__ float g_bias[Hh];
__device__ float g_stat[2 * Hh];
__device__ float g_bnA[Hh], g_bnB[Hh];
__device__ int g_off[Nn + 1];
__device__ int g_cur[Nn];
__device__ int g_epk[Ee];
__device__ int g_bsum[64];

// ---- zero helpers ----
__global__ void k_zero_cnt() {
    int i = blockIdx.x * blockDim.x + threadIdx.x;
    if (i < Nn * Rr) g_cnt[i] = 0.f;
}
__global__ void k_zero_stat() {
    int i = threadIdx.x;
    if (i < 2 * Hh) g_stat[i] = 0.f;
}

// ---- per-(dst,relation) counts ----
__global__ void k_count(const int* __restrict__ ei, const int* __restrict__ et) {
    int e = blockIdx.x * blockDim.x + threadIdx.x;
    if (e < Ee) {
        int d = ei[Ee + e];
        int r = et[e];
        atomicAdd(&g_cnt[d * Rr + r], 1.0f);
    }
}

// ---- CSR build ----
__global__ void __launch_bounds__(256) k_scan1() {
    __shared__ int sh[256];
    int tid = threadIdx.x;
    int base = blockIdx.x * 1024;
    int d[4];
    int local = 0;
#pragma unroll
    for (int j = 0; j < 4; j++) {
        int n = base + tid * 4 + j;
        int deg = 0;
        if (n < Nn) {
#pragma unroll
            for (int r = 0; r < Rr; r++) deg += (int)g_cnt[n * Rr + r];
        }
        d[j] = deg;
        local += deg;
    }
    sh[tid] = local;
    __syncthreads();
    for (int s = 1; s < 256; s <<= 1) {
        int v = (tid >= s) ? sh[tid - s] : 0;
        __syncthreads();
        sh[tid] += v;
        __syncthreads();
    }
    int run = sh[tid] - local;
    if (tid == 255) g_bsum[blockIdx.x] = sh[255];
#pragma unroll
    for (int j = 0; j < 4; j++) {
        int n = base + tid * 4 + j;
        if (n < Nn) g_off[n] = run;
        run += d[j];
    }
}

__global__ void k_scan2() {
    __shared__ int sh[64];
    int tid = threadIdx.x;
    int v = (tid < 49) ? g_bsum[tid] : 0;
    sh[tid] = v;
    __syncthreads();
    for (int s = 1; s < 64; s <<= 1) {
        int u = (tid >= s) ? sh[tid - s] : 0;
        __syncthreads();
        sh[tid] += u;
        __syncthreads();
    }
    if (tid < 49) g_bsum[tid] = sh[tid] - v;
    if (tid == 0) g_off[Nn] = Ee;
}

__global__ void k_scan3() {
    int n = blockIdx.x * blockDim.x + threadIdx.x;
    if (n < Nn) {
        int o = g_off[n] + g_bsum[n >> 10];
        g_off[n] = o;
        g_cur[n] = o;
    }
}

__global__ void k_place(const int* __restrict__ ei, const int* __restrict__ et) {
    int e = blockIdx.x * blockDim.x + threadIdx.x;
    if (e < Ee) {
        int d = ei[Ee + e];
        int s = ei[e];
        int r = et[e];
        int pos = atomicAdd(&g_cur[d], 1);
        g_epk[pos] = s | (r << 24);
    }
}

// ---- gather-aggregate (packed f32x2 over channel pairs, 64 threads/node) ----
template <bool FROM_XR>
__global__ void __launch_bounds__(64) k_agg(const float* __restrict__ X,
                                            const float* __restrict__ comp) {
    int n = blockIdx.x;
    int c2 = threadIdx.x;            // channel pair index (channels 2c2, 2c2+1)
    __shared__ u64 coefp[Rr * 4];    // [r][b], both halves = coef
    __shared__ int se[32];
    if (c2 < Rr * Bb) {
        int r = c2 >> 2, b = c2 & 3;
        float cc = g_cnt[n * Rr + r];
        coefp[c2] = pack2(comp[r * Bb + b] / fmaxf(cc, 1.0f));
    }
    int start = g_off[n], end = g_off[n + 1];
    __syncthreads();
    const float* Xp = FROM_XR ? g_xr : X;
    u64 a0 = 0, a1 = 0, a2 = 0, a3 = 0;
    for (int base = start; base < end; base += 32) {
        int m = min(32, end - base);
        if (c2 < m) se[c2] = g_epk[base + c2];
        __syncthreads();
        int i = 0;
        for (; i + 1 < m; i += 2) {
            int pk0 = se[i], pk1 = se[i + 1];
            u64 xv0 = *(const u64*)(Xp + (size_t)(pk0 & 0xFFFFFF) * Hh + 2 * c2);
            u64 xv1 = *(const u64*)(Xp + (size_t)(pk1 & 0xFFFFFF) * Hh + 2 * c2);
            int q0 = (pk0 >> 24) << 2, q1 = (pk1 >> 24) << 2;
            a0 = fma2(coefp[q0 + 0], xv0, a0);
            a1 = fma2(coefp[q0 + 1], xv0, a1);
            a2 = fma2(coefp[q0 + 2], xv0, a2);
            a3 = fma2(coefp[q0 + 3], xv0, a3);
            a0 = fma2(coefp[q1 + 0], xv1, a0);
            a1 = fma2(coefp[q1 + 1], xv1, a1);
            a2 = fma2(coefp[q1 + 2], xv1, a2);
            a3 = fma2(coefp[q1 + 3], xv1, a3);
        }
        if (i < m) {
            int pk = se[i];
            u64 xv = *(const u64*)(Xp + (size_t)(pk & 0xFFFFFF) * Hh + 2 * c2);
            int q = (pk >> 24) << 2;
            a0 = fma2(coefp[q + 0], xv, a0);
            a1 = fma2(coefp[q + 1], xv, a1);
            a2 = fma2(coefp[q + 2], xv, a2);
            a3 = fma2(coefp[q + 3], xv, a3);
        }
        __syncthreads();
    }
    size_t t = (size_t)n * 512 + 2 * c2;
    *(float2*)&g_T[t +   0] = make_float2(lo2(a0), hi2(a0));
    *(float2*)&g_T[t + 128] = make_float2(lo2(a1), hi2(a1));
    *(float2*)&g_T[t + 256] = make_float2(lo2(a2), hi2(a2));
    *(float2*)&g_T[t + 384] = make_float2(lo2(a3), hi2(a3));
}

// ---- prep: W = root + skip_w ; bias = bias + skip_b ----
__global__ void k_prep(const float* __restrict__ root, const float* __restrict__ skw,
                       const float* __restrict__ bias, const float* __restrict__ skb) {
    int i = blockIdx.x * blockDim.x + threadIdx.x;
    if (i < Hh * Hh) g_W[i] = root[i] + skw[i];
    if (i < Hh) g_bias[i] = bias[i] + skb[i];
}

// ---- SGEMM with packed f32x2 (FFMA2): C[M,128] = [T | X] @ [bases ; W] + bias
//      M=50000, K=640, N=128; 64x128 tile, 256 threads, 8 rows x 4 cols/thread,
//      accumulators packed over row pairs ----
template <bool FROM_XR>
__global__ void __launch_bounds__(256)
k_gemm(const float* __restrict__ Asec, const float* __restrict__ B1,
       float* __restrict__ C) {
    __shared__ float As[32 * 68];      // k-major, stride 68 (each k-row 16B aligned)
    __shared__ float Bs[32 * 128];
    int tid = threadIdx.x;
    int r0 = (tid >> 5) * 8;           // warp-uniform row group
    int cg = tid & 31;                 // col group (4 floats)
    int m0 = blockIdx.x * 64;
    u64 accp[4][4];                    // [rowpair][col] packed (row r0+2i, r0+2i+1)
#pragma unroll
    for (int i = 0; i < 4; i++)
#pragma unroll
        for (int c = 0; c < 4; c++) accp[i][c] = 0ull;

    const float4* xsec4 = FROM_XR ? (const float4*)g_xr : (const float4*)Asec;

    for (int kc = 0; kc < 20; kc++) {
        int kk = kc * 32;
#pragma unroll
        for (int t = 0; t < 2; t++) {
            int idx = tid + t * 256;
            int row = idx >> 3, kq = idx & 7;
            int n = m0 + row;
            float4 v = make_float4(0.f, 0.f, 0.f, 0.f);
            if (n < Nn) {
                if (kc < 16) v = *(const float4*)&g_T[(size_t)n * 512 + kk + kq * 4];
                else         v = xsec4[(size_t)n * 32 + ((kk - 512) >> 2) + kq];
            }
            int kb = kq * 4;
            As[(kb + 0) * 68 + row] = v.x;
            As[(kb + 1) * 68 + row] = v.y;
            As[(kb + 2) * 68 + row] = v.z;
            As[(kb + 3) * 68 + row] = v.w;
        }
#pragma unroll
        for (int t = 0; t < 4; t++) {
            int idx = tid + t * 256;
            int kr = idx >> 5, fq = idx & 31;
            const float* Bsrc = (kc < 16) ? &B1[(size_t)(kk + kr) * 128]
                                          : &g_W[(size_t)(kk - 512 + kr) * 128];
            ((float4*)Bs)[kr * 32 + fq] = ((const float4*)Bsrc)[fq];
        }
        __syncthreads();
#pragma unroll
        for (int k = 0; k < 32; k++) {
            float4 b = ((float4*)Bs)[k * 32 + cg];
            // row pairs natural from 16B smem loads (warp-uniform broadcast)
            ulonglong2 a01 = *(const ulonglong2*)&As[k * 68 + r0];
            ulonglong2 a23 = *(const ulonglong2*)&As[k * 68 + r0 + 4];
            u64 ap[4] = {a01.x, a01.y, a23.x, a23.y};
            u64 bp[4] = {pack2(b.x), pack2(b.y), pack2(b.z), pack2(b.w)};
#pragma unroll
            for (int i = 0; i < 4; i++) {
                accp[i][0] = fma2(ap[i], bp[0], accp[i][0]);
                accp[i][1] = fma2(ap[i], bp[1], accp[i][1]);
                accp[i][2] = fma2(ap[i], bp[2], accp[i][2]);
                accp[i][3] = fma2(ap[i], bp[3], accp[i][3]);
            }
        }
        __syncthreads();
    }
    float4 bv = *(const float4*)&g_bias[cg * 4];
#pragma unroll
    for (int i = 0; i < 4; i++) {
        int n0 = m0 + r0 + 2 * i;
        if (n0 < Nn) {
            float4 o0 = make_float4(lo2(accp[i][0]) + bv.x, lo2(accp[i][1]) + bv.y,
                                    lo2(accp[i][2]) + bv.z, lo2(accp[i][3]) + bv.w);
            *(float4*)&C[(size_t)n0 * 128 + cg * 4] = o0;
        }
        if (n0 + 1 < Nn) {
            float4 o1 = make_float4(hi2(accp[i][0]) + bv.x, hi2(accp[i][1]) + bv.y,
                                    hi2(accp[i][2]) + bv.z, hi2(accp[i][3]) + bv.w);
            *(float4*)&C[(size_t)(n0 + 1) * 128 + cg * 4] = o1;
        }
    }
}

// ---- BatchNorm ----
#define BN_ROWS 256
__global__ void k_bnstats(const float* __restrict__ X) {
    int c = threadIdx.x;
    int n0 = blockIdx.x * BN_ROWS;
    float s = 0.f, s2 = 0.f;
    for (int i = 0; i < BN_ROWS; i++) {
        int n = n0 + i;
        if (n < Nn) {
            float v = X[(size_t)n * Hh + c];
            s += v;
            s2 += v * v;
        }
    }
    atomicAdd(&g_stat[c], s);
    atomicAdd(&g_stat[Hh + c], s2);
}

__global__ void k_bnfin(const float* __restrict__ gamma, const float* __restrict__ beta) {
    int c = threadIdx.x;
    float m = g_stat[c] * (1.0f / Nn);
    float var = g_stat[Hh + c] * (1.0f / Nn) - m * m;
    float a = gamma[c] * rsqrtf(var + 1e-5f);
    g_bnA[c] = a;
    g_bnB[c] = beta[c] - m * a;
}

__global__ void k_bnapply(const float* __restrict__ X) {
    size_t i = (size_t)blockIdx.x * blockDim.x + threadIdx.x;
    if (i >= (size_t)Nn * 32) return;
    int cq = ((int)(i & 31)) * 4;
    float4 v = ((const float4*)X)[i];
    float4 a = *(const float4*)&g_bnA[cq];
    float4 b = *(const float4*)&g_bnB[cq];
    v.x = fmaxf(a.x * v.x + b.x, 0.f);
    v.y = fmaxf(a.y * v.y + b.y, 0.f);
    v.z = fmaxf(a.z * v.z + b.z, 0.f);
    v.w = fmaxf(a.w * v.w + b.w, 0.f);
    ((float4*)g_xr)[i] = v;
}

extern "C" void kernel_launch(void* const* d_in, const int* in_sizes, int n_in,
                              void* d_out, int out_size) {
    const float* x       = (const float*)d_in[0];
    const int*   ei      = (const int*)d_in[1];
    const int*   et      = (const int*)d_in[2];
    const float* comp1   = (const float*)d_in[3];
    const float* bases1  = (const float*)d_in[4];
    const float* root1   = (const float*)d_in[5];
    const float* bias1   = (const float*)d_in[6];
    const float* skip1_w = (const float*)d_in[7];
    const float* skip1_b = (const float*)d_in[8];
    const float* gamma   = (const float*)d_in[9];
    const float* beta    = (const float*)d_in[10];
    const float* comp2   = (const float*)d_in[11];
    const float* bases2  = (const float*)d_in[12];
    const float* root2   = (const float*)d_in[13];
    const float* bias2   = (const float*)d_in[14];
    const float* skip2_w = (const float*)d_in[15];
    const float* skip2_b = (const float*)d_in[16];

    float* out_h  = (float*)d_out;
    float* out_x2 = (float*)d_out + (size_t)Nn * Hh;

    // ---- CSR build (shared between layers) ----
    k_zero_cnt<<<(Nn * Rr + 255) / 256, 256>>>();
    k_count<<<(Ee + 255) / 256, 256>>>(ei, et);
    k_scan1<<<(Nn + 1023) / 1024, 256>>>();
    k_scan2<<<1, 64>>>();
    k_scan3<<<(Nn + 255) / 256, 256>>>();
    k_place<<<(Ee + 255) / 256, 256>>>(ei, et);

    // ---- layer 1 ----
    k_prep<<<64, 256>>>(root1, skip1_w, bias1, skip1_b);
    k_agg<false><<<Nn, 64>>>(x, comp1);
    k_gemm<false><<<(Nn + 63) / 64, 256>>>(x, bases1, out_h);

    // ---- BatchNorm + ReLU ----
    k_zero_stat<<<1, 256>>>();
    k_bnstats<<<(Nn + BN_ROWS - 1) / BN_ROWS, 128>>>(out_h);
    k_bnfin<<<1, 128>>>(gamma, beta);
    k_bnapply<<<(unsigned)(((size_t)Nn * 32 + 255) / 256), 256>>>(out_h);

    // ---- layer 2 ----
    k_prep<<<64, 256>>>(root2, skip2_w, bias2, skip2_b);
    k_agg<true><<<Nn, 64>>>(nullptr, comp2);
    k_gemm<true><<<(Nn + 63) / 64, 256>>>(nullptr, bases2, out_x2);
}

// round 12
// speedup vs baseline: 1.9119x; 1.3436x over previous
#include <cuda_runtime.h>
#include <cuda_bf16.h>
#include <cstddef>
#include <cstdint>

#define Nn 50000
#define Ee 800000
#define Rr 8
#define Bb 4
#define Hh 128

typedef unsigned long long u64;

// ================= helpers =================
__device__ __forceinline__ u64 pack2(float v) {
    u64 r; asm("mov.b64 %0, {%1, %1};" : "=l"(r) : "f"(v)); return r;
}
__device__ __forceinline__ u64 fma2(u64 a, u64 b, u64 c) {
    u64 d; asm("fma.rn.f32x2 %0, %1, %2, %3;" : "=l"(d) : "l"(a), "l"(b), "l"(c)); return d;
}
__device__ __forceinline__ float lo2(u64 v) { return __uint_as_float((unsigned)v); }
__device__ __forceinline__ float hi2(u64 v) { return __uint_as_float((unsigned)(v >> 32)); }

__device__ __forceinline__ uint32_t bf2u(__nv_bfloat162 v) {
    return *reinterpret_cast<uint32_t*>(&v);
}
__device__ __forceinline__ uint32_t s2u(const void* p) {
    uint32_t a;
    asm("{ .reg .u64 t; cvta.to.shared.u64 t, %1; cvt.u32.u64 %0, t; }" : "=r"(a) : "l"(p));
    return a;
}
__device__ __forceinline__ void ldsm4(uint32_t* r, uint32_t addr) {
    asm volatile("ldmatrix.sync.aligned.m8n8.x4.shared.b16 {%0,%1,%2,%3}, [%4];"
                 : "=r"(r[0]), "=r"(r[1]), "=r"(r[2]), "=r"(r[3]) : "r"(addr));
}
__device__ __forceinline__ void mma16816(float* c, const uint32_t* a, const uint32_t* b) {
    asm volatile(
        "mma.sync.aligned.m16n8k16.row.col.f32.bf16.bf16.f32 "
        "{%0,%1,%2,%3}, {%4,%5,%6,%7}, {%8,%9}, {%0,%1,%2,%3};"
        : "+f"(c[0]), "+f"(c[1]), "+f"(c[2]), "+f"(c[3])
        : "r"(a[0]), "r"(a[1]), "r"(a[2]), "r"(a[3]), "r"(b[0]), "r"(b[1]));
}

// ================= device scratch =================
__device__ float g_T[(size_t)Nn * Bb * Hh];
__device__ float g_cnt[Nn * Rr];
__device__ float g_xr[(size_t)Nn * Hh];
__device__ float g_bias[Hh];
__device__ float g_stat[2 * Hh];
__device__ float g_bnA[Hh], g_bnB[Hh];
__device__ int g_off[Nn + 1];
__device__ int g_cur[Nn];
__device__ int g_epk[Ee];
__device__ int g_bsum[64];
// weights hi/lo bf16, per-32k-chunk images: [kc][n(128)][40 pad], k contiguous
__device__ __nv_bfloat16 g_WbHi[20 * 128 * 40];
__device__ __nv_bfloat16 g_WbLo[20 * 128 * 40];

// ================= zero helpers =================
__global__ void k_zero_cnt() {
    int i = blockIdx.x * blockDim.x + threadIdx.x;
    if (i < Nn * Rr) g_cnt[i] = 0.f;
}
__global__ void k_zero_stat() {
    int i = threadIdx.x;
    if (i < 2 * Hh) g_stat[i] = 0.f;
}

// ================= counts =================
__global__ void k_count(const int* __restrict__ ei, const int* __restrict__ et) {
    int e = blockIdx.x * blockDim.x + threadIdx.x;
    if (e < Ee) {
        int d = ei[Ee + e];
        int r = et[e];
        atomicAdd(&g_cnt[d * Rr + r], 1.0f);
    }
}

// ================= CSR build =================
__global__ void __launch_bounds__(256) k_scan1() {
    __shared__ int sh[256];
    int tid = threadIdx.x;
    int base = blockIdx.x * 1024;
    int d[4];
    int local = 0;
#pragma unroll
    for (int j = 0; j < 4; j++) {
        int n = base + tid * 4 + j;
        int deg = 0;
        if (n < Nn) {
#pragma unroll
            for (int r = 0; r < Rr; r++) deg += (int)g_cnt[n * Rr + r];
        }
        d[j] = deg;
        local += deg;
    }
    sh[tid] = local;
    __syncthreads();
    for (int s = 1; s < 256; s <<= 1) {
        int v = (tid >= s) ? sh[tid - s] : 0;
        __syncthreads();
        sh[tid] += v;
        __syncthreads();
    }
    int run = sh[tid] - local;
    if (tid == 255) g_bsum[blockIdx.x] = sh[255];
#pragma unroll
    for (int j = 0; j < 4; j++) {
        int n = base + tid * 4 + j;
        if (n < Nn) g_off[n] = run;
        run += d[j];
    }
}

__global__ void k_scan2() {
    __shared__ int sh[64];
    int tid = threadIdx.x;
    int v = (tid < 49) ? g_bsum[tid] : 0;
    sh[tid] = v;
    __syncthreads();
    for (int s = 1; s < 64; s <<= 1) {
        int u = (tid >= s) ? sh[tid - s] : 0;
        __syncthreads();
        sh[tid] += u;
        __syncthreads();
    }
    if (tid < 49) g_bsum[tid] = sh[tid] - v;
    if (tid == 0) g_off[Nn] = Ee;
}

__global__ void k_scan3() {
    int n = blockIdx.x * blockDim.x + threadIdx.x;
    if (n < Nn) {
        int o = g_off[n] + g_bsum[n >> 10];
        g_off[n] = o;
        g_cur[n] = o;
    }
}

__global__ void k_place(const int* __restrict__ ei, const int* __restrict__ et) {
    int e = blockIdx.x * blockDim.x + threadIdx.x;
    if (e < Ee) {
        int d = ei[Ee + e];
        int s = ei[e];
        int r = et[e];
        int pos = atomicAdd(&g_cur[d], 1);
        g_epk[pos] = s | (r << 24);
    }
}

// ================= gather-aggregate (f32x2) =================
template <bool FROM_XR>
__global__ void __launch_bounds__(64) k_agg(const float* __restrict__ X,
                                            const float* __restrict__ comp) {
    int n = blockIdx.x;
    int c2 = threadIdx.x;
    __shared__ u64 coefp[Rr * 4];
    __shared__ int se[32];
    if (c2 < Rr * Bb) {
        int r = c2 >> 2, b = c2 & 3;
        float cc = g_cnt[n * Rr + r];
        coefp[c2] = pack2(comp[r * Bb + b] / fmaxf(cc, 1.0f));
    }
    int start = g_off[n], end = g_off[n + 1];
    __syncthreads();
    const float* Xp = FROM_XR ? g_xr : X;
    u64 a0 = 0, a1 = 0, a2 = 0, a3 = 0;
    for (int base = start; base < end; base += 32) {
        int m = min(32, end - base);
        if (c2 < m) se[c2] = g_epk[base + c2];
        __syncthreads();
        int i = 0;
        for (; i + 1 < m; i += 2) {
            int pk0 = se[i], pk1 = se[i + 1];
            u64 xv0 = *(const u64*)(Xp + (size_t)(pk0 & 0xFFFFFF) * Hh + 2 * c2);
            u64 xv1 = *(const u64*)(Xp + (size_t)(pk1 & 0xFFFFFF) * Hh + 2 * c2);
            int q0 = (pk0 >> 24) << 2, q1 = (pk1 >> 24) << 2;
            a0 = fma2(coefp[q0 + 0], xv0, a0);
            a1 = fma2(coefp[q0 + 1], xv0, a1);
            a2 = fma2(coefp[q0 + 2], xv0, a2);
            a3 = fma2(coefp[q0 + 3], xv0, a3);
            a0 = fma2(coefp[q1 + 0], xv1, a0);
            a1 = fma2(coefp[q1 + 1], xv1, a1);
            a2 = fma2(coefp[q1 + 2], xv1, a2);
            a3 = fma2(coefp[q1 + 3], xv1, a3);
        }
        if (i < m) {
            int pk = se[i];
            u64 xv = *(const u64*)(Xp + (size_t)(pk & 0xFFFFFF) * Hh + 2 * c2);
            int q = (pk >> 24) << 2;
            a0 = fma2(coefp[q + 0], xv, a0);
            a1 = fma2(coefp[q + 1], xv, a1);
            a2 = fma2(coefp[q + 2], xv, a2);
            a3 = fma2(coefp[q + 3], xv, a3);
        }
        __syncthreads();
    }
    size_t t = (size_t)n * 512 + 2 * c2;
    *(float2*)&g_T[t +   0] = make_float2(lo2(a0), hi2(a0));
    *(float2*)&g_T[t + 128] = make_float2(lo2(a1), hi2(a1));
    *(float2*)&g_T[t + 256] = make_float2(lo2(a2), hi2(a2));
    *(float2*)&g_T[t + 384] = make_float2(lo2(a3), hi2(a3));
}

// ================= weight prep: hi/lo bf16 split into padded chunk images ======
// B operand = W^T: image[kc][n=out col(128)][c=k in chunk(32), pad to 40].
// W rows 0..511 = bases (k = b*128+d), rows 512..639 = root + skip.
__global__ void k_prepW(const float* __restrict__ bases, const float* __restrict__ root,
                        const float* __restrict__ skw, const float* __restrict__ bias,
                        const float* __restrict__ skb) {
    int e = blockIdx.x * blockDim.x + threadIdx.x;
    if (e < 128) g_bias[e] = bias[e] + skb[e];
    if (e >= 20 * 128 * 32) return;
    int kc = e >> 12;
    int rem = e & 4095;
    int n = rem >> 5;      // output col
    int c = rem & 31;      // k within chunk
    int k = kc * 32 + c;
    float w = (k < 512) ? bases[(size_t)k * 128 + n]
                        : root[(size_t)(k - 512) * 128 + n] + skw[(size_t)(k - 512) * 128 + n];
    __nv_bfloat16 hi = __float2bfloat16(w);
    float lo = w - __bfloat162float(hi);
    int idx = kc * (128 * 40) + n * 40 + c;
    g_WbHi[idx] = hi;
    g_WbLo[idx] = __float2bfloat16(lo);
}

// ================= HMMA GEMM via mma.sync bf16x3 =================
// C[M,128] = [T | X] @ W + bias ; M=50000 (tiles 128), K=640 (20 chunks x32), N=128.
// 512 threads = 16 warps (4x4), warp tile 32x32.
// smem: A hi/lo + B hi/lo, each [128][40] bf16 (80B rows, conflict-free ldmatrix).
#define AS_STRIDE 40

template <bool FROM_XR>
__global__ void __launch_bounds__(512)
k_hmma(const float* __restrict__ Asec, float* __restrict__ C) {
    __shared__ __align__(16) __nv_bfloat16 sAhi[128 * AS_STRIDE];
    __shared__ __align__(16) __nv_bfloat16 sAlo[128 * AS_STRIDE];
    __shared__ __align__(16) __nv_bfloat16 sBhi[128 * AS_STRIDE];
    __shared__ __align__(16) __nv_bfloat16 sBlo[128 * AS_STRIDE];

    int t = threadIdx.x;
    int lane = t & 31, w = t >> 5;
    int wm = w >> 2, wn = w & 3;
    int m0 = blockIdx.x * 128;

    // staging coords
    int srow = t >> 2, sq = t & 3;
    bool rowok = (m0 + srow) < Nn;
    const float* xsec = FROM_XR ? g_xr : Asec;

    // ldmatrix lane-derived byte offsets
    int arow = wm * 32 + (lane & 15);
    int akb  = (lane >> 4) * 16;                         // k half: +8 cols = 16B
    int brow = wn * 32 + (lane & 7) + ((lane >> 4) << 3);
    int bkb  = ((lane >> 3) & 1) * 16;
    uint32_t aHi = s2u(sAhi) + arow * 80 + akb;
    uint32_t aLo = s2u(sAlo) + arow * 80 + akb;
    uint32_t bHi = s2u(sBhi) + brow * 80 + bkb;
    uint32_t bLo = s2u(sBlo) + brow * 80 + bkb;

    float cc[2][4][4];
#pragma unroll
    for (int i = 0; i < 2; i++)
#pragma unroll
        for (int j = 0; j < 4; j++)
#pragma unroll
            for (int k = 0; k < 4; k++) cc[i][j][k] = 0.f;

    for (int kc = 0; kc < 20; kc++) {
        __syncthreads();
        // ---- stage A: 128 rows x 32 fp32 -> hi/lo bf16 ----
        {
            float4 va = make_float4(0, 0, 0, 0), vb = va;
            if (rowok) {
                const float4* src = (kc < 16)
                    ? (const float4*)&g_T[(size_t)(m0 + srow) * 512 + kc * 32 + sq * 8]
                    : (const float4*)&xsec[(size_t)(m0 + srow) * 128 + (kc - 16) * 32 + sq * 8];
                va = src[0];
                vb = src[1];
            }
            __nv_bfloat162 h0 = __float22bfloat162_rn(make_float2(va.x, va.y));
            __nv_bfloat162 h1 = __float22bfloat162_rn(make_float2(va.z, va.w));
            __nv_bfloat162 h2 = __float22bfloat162_rn(make_float2(vb.x, vb.y));
            __nv_bfloat162 h3 = __float22bfloat162_rn(make_float2(vb.z, vb.w));
            float2 f0 = __bfloat1622float2(h0), f1 = __bfloat1622float2(h1);
            float2 f2 = __bfloat1622float2(h2), f3 = __bfloat1622float2(h3);
            __nv_bfloat162 l0 = __float22bfloat162_rn(make_float2(va.x - f0.x, va.y - f0.y));
            __nv_bfloat162 l1 = __float22bfloat162_rn(make_float2(va.z - f1.x, va.w - f1.y));
            __nv_bfloat162 l2 = __float22bfloat162_rn(make_float2(vb.x - f2.x, vb.y - f2.y));
            __nv_bfloat162 l3 = __float22bfloat162_rn(make_float2(vb.z - f3.x, vb.w - f3.y));
            uint4 hv = make_uint4(bf2u(h0), bf2u(h1), bf2u(h2), bf2u(h3));
            uint4 lv = make_uint4(bf2u(l0), bf2u(l1), bf2u(l2), bf2u(l3));
            *(uint4*)&sAhi[srow * AS_STRIDE + sq * 8] = hv;
            *(uint4*)&sAlo[srow * AS_STRIDE + sq * 8] = lv;
        }
        // ---- stage B: linear copy of padded chunk image (640 uint4 each) ----
        {
            const uint4* wbh = (const uint4*)&g_WbHi[kc * (128 * AS_STRIDE)];
            const uint4* wbl = (const uint4*)&g_WbLo[kc * (128 * AS_STRIDE)];
            ((uint4*)sBhi)[t] = wbh[t];
            ((uint4*)sBlo)[t] = wbl[t];
            if (t < 128) {
                ((uint4*)sBhi)[512 + t] = wbh[512 + t];
                ((uint4*)sBlo)[512 + t] = wbl[512 + t];
            }
        }
        __syncthreads();

        // ---- compute: 2 k16-steps per chunk ----
#pragma unroll
        for (int s = 0; s < 2; s++) {
            uint32_t kb = s * 32;  // 16 cols * 2B
            uint32_t ah[2][4], al[2][4], bh[2][4], bl[2][4];
#pragma unroll
            for (int mt = 0; mt < 2; mt++) {
                ldsm4(ah[mt], aHi + mt * (16 * 80) + kb);
                ldsm4(al[mt], aLo + mt * (16 * 80) + kb);
            }
#pragma unroll
            for (int p = 0; p < 2; p++) {
                ldsm4(bh[p], bHi + p * (16 * 80) + kb);
                ldsm4(bl[p], bLo + p * (16 * 80) + kb);
            }
#pragma unroll
            for (int mt = 0; mt < 2; mt++) {
#pragma unroll
                for (int p = 0; p < 2; p++) {
                    mma16816(cc[mt][p * 2], ah[mt], &bh[p][0]);
                    mma16816(cc[mt][p * 2], ah[mt], &bl[p][0]);
                    mma16816(cc[mt][p * 2], al[mt], &bh[p][0]);
                    mma16816(cc[mt][p * 2 + 1], ah[mt], &bh[p][2]);
                    mma16816(cc[mt][p * 2 + 1], ah[mt], &bl[p][2]);
                    mma16816(cc[mt][p * 2 + 1], al[mt], &bh[p][2]);
                }
            }
        }
    }

    // ---- epilogue ----
#pragma unroll
    for (int mt = 0; mt < 2; mt++) {
#pragma unroll
        for (int nt = 0; nt < 4; nt++) {
            int mrow = m0 + wm * 32 + mt * 16 + (lane >> 2);
            int ncol = wn * 32 + nt * 8 + (lane & 3) * 2;
            float2 bv = *(const float2*)&g_bias[ncol];
            if (mrow < Nn)
                *(float2*)&C[(size_t)mrow * 128 + ncol] =
                    make_float2(cc[mt][nt][0] + bv.x, cc[mt][nt][1] + bv.y);
            if (mrow + 8 < Nn)
                *(float2*)&C[(size_t)(mrow + 8) * 128 + ncol] =
                    make_float2(cc[mt][nt][2] + bv.x, cc[mt][nt][3] + bv.y);
        }
    }
}

// ================= BatchNorm =================
#define BN_ROWS 32
__global__ void k_bnstats(const float* __restrict__ X) {
    int c = threadIdx.x;
    int n0 = blockIdx.x * BN_ROWS;
    float s = 0.f, s2 = 0.f;
#pragma unroll 4
    for (int i = 0; i < BN_ROWS; i++) {
        int n = n0 + i;
        if (n < Nn) {
            float v = X[(size_t)n * Hh + c];
            s += v;
            s2 += v * v;
        }
    }
    atomicAdd(&g_stat[c], s);
    atomicAdd(&g_stat[Hh + c], s2);
}

__global__ void k_bnfin(const float* __restrict__ gamma, const float* __restrict__ beta) {
    int c = threadIdx.x;
    float m = g_stat[c] * (1.0f / Nn);
    float var = g_stat[Hh + c] * (1.0f / Nn) - m * m;
    float a = gamma[c] * rsqrtf(var + 1e-5f);
    g_bnA[c] = a;
    g_bnB[c] = beta[c] - m * a;
}

__global__ void k_bnapply(const float* __restrict__ X) {
    size_t i = (size_t)blockIdx.x * blockDim.x + threadIdx.x;
    if (i >= (size_t)Nn * 32) return;
    int cq = ((int)(i & 31)) * 4;
    float4 v = ((const float4*)X)[i];
    float4 a = *(const float4*)&g_bnA[cq];
    float4 b = *(const float4*)&g_bnB[cq];
    v.x = fmaxf(a.x * v.x + b.x, 0.f);
    v.y = fmaxf(a.y * v.y + b.y, 0.f);
    v.z = fmaxf(a.z * v.z + b.z, 0.f);
    v.w = fmaxf(a.w * v.w + b.w, 0.f);
    ((float4*)g_xr)[i] = v;
}

extern "C" void kernel_launch(void* const* d_in, const int* in_sizes, int n_in,
                              void* d_out, int out_size) {
    const float* x       = (const float*)d_in[0];
    const int*   ei      = (const int*)d_in[1];
    const int*   et      = (const int*)d_in[2];
    const float* comp1   = (const float*)d_in[3];
    const float* bases1  = (const float*)d_in[4];
    const float* root1   = (const float*)d_in[5];
    const float* bias1   = (const float*)d_in[6];
    const float* skip1_w = (const float*)d_in[7];
    const float* skip1_b = (const float*)d_in[8];
    const float* gamma   = (const float*)d_in[9];
    const float* beta    = (const float*)d_in[10];
    const float* comp2   = (const float*)d_in[11];
    const float* bases2  = (const float*)d_in[12];
    const float* root2   = (const float*)d_in[13];
    const float* bias2   = (const float*)d_in[14];
    const float* skip2_w = (const float*)d_in[15];
    const float* skip2_b = (const float*)d_in[16];

    float* out_h  = (float*)d_out;
    float* out_x2 = (float*)d_out + (size_t)Nn * Hh;

    const int MTILES = (Nn + 127) / 128;

    // ---- CSR build ----
    k_zero_cnt<<<(Nn * Rr + 255) / 256, 256>>>();
    k_count<<<(Ee + 255) / 256, 256>>>(ei, et);
    k_scan1<<<(Nn + 1023) / 1024, 256>>>();
    k_scan2<<<1, 64>>>();
    k_scan3<<<(Nn + 255) / 256, 256>>>();
    k_place<<<(Ee + 255) / 256, 256>>>(ei, et);

    // ---- layer 1 ----
    k_prepW<<<(20 * 128 * 32 + 255) / 256, 256>>>(bases1, root1, skip1_w, bias1, skip1_b);
    k_agg<false><<<Nn, 64>>>(x, comp1);
    k_hmma<false><<<MTILES, 512>>>(x, out_h);

    // ---- BatchNorm + ReLU ----
    k_zero_stat<<<1, 256>>>();
    k_bnstats<<<(Nn + BN_ROWS - 1) / BN_ROWS, 128>>>(out_h);
    k_bnfin<<<1, 128>>>(gamma, beta);
    k_bnapply<<<(unsigned)(((size_t)Nn * 32 + 255) / 256), 256>>>(out_h);

    // ---- layer 2 ----
    k_prepW<<<(20 * 128 * 32 + 255) / 256, 256>>>(bases2, root2, skip2_w, bias2, skip2_b);
    k_agg<true><<<Nn, 64>>>(nullptr, comp2);
    k_hmma<true><<<MTILES, 512>>>(nullptr, out_x2);
}

// round 14
// speedup vs baseline: 2.4667x; 1.2902x over previous
#include <cuda_runtime.h>
#include <cuda_bf16.h>
#include <cstddef>
#include <cstdint>

#define Nn 50000
#define NP 50048          // padded rows (391 * 128)
#define Ee 800000
#define Rr 8
#define Bb 4
#define Hh 128
#define PS 40             // padded image stride (elems); 80B rows, conflict-free ldmatrix

typedef unsigned long long u64;

// ================= helpers =================
__device__ __forceinline__ u64 pack2(float v) {
    u64 r; asm("mov.b64 %0, {%1, %1};" : "=l"(r) : "f"(v)); return r;
}
__device__ __forceinline__ u64 fma2(u64 a, u64 b, u64 c) {
    u64 d; asm("fma.rn.f32x2 %0, %1, %2, %3;" : "=l"(d) : "l"(a), "l"(b), "l"(c)); return d;
}
__device__ __forceinline__ float lo2(u64 v) { return __uint_as_float((unsigned)v); }
__device__ __forceinline__ float hi2(u64 v) { return __uint_as_float((unsigned)(v >> 32)); }
__device__ __forceinline__ uint32_t bf2u(__nv_bfloat162 v) {
    return *reinterpret_cast<uint32_t*>(&v);
}
__device__ __forceinline__ uint32_t s2u(const void* p) {
    uint32_t a;
    asm("{ .reg .u64 t; cvta.to.shared.u64 t, %1; cvt.u32.u64 %0, t; }" : "=r"(a) : "l"(p));
    return a;
}
__device__ __forceinline__ void ldsm4(uint32_t* r, uint32_t addr) {
    asm volatile("ldmatrix.sync.aligned.m8n8.x4.shared.b16 {%0,%1,%2,%3}, [%4];"
                 : "=r"(r[0]), "=r"(r[1]), "=r"(r[2]), "=r"(r[3]) : "r"(addr));
}
__device__ __forceinline__ void mma16816(float* c, const uint32_t* a, const uint32_t* b) {
    asm volatile(
        "mma.sync.aligned.m16n8k16.row.col.f32.bf16.bf16.f32 "
        "{%0,%1,%2,%3}, {%4,%5,%6,%7}, {%8,%9}, {%0,%1,%2,%3};"
        : "+f"(c[0]), "+f"(c[1]), "+f"(c[2]), "+f"(c[3])
        : "r"(a[0]), "r"(a[1]), "r"(a[2]), "r"(a[3]), "r"(b[0]), "r"(b[1]));
}
__device__ __forceinline__ void cpa16(uint32_t dst, const void* src) {
    asm volatile("cp.async.cg.shared.global [%0], [%1], 16;" :: "r"(dst), "l"(src));
}
__device__ __forceinline__ void split_pair(float x, float y, uint32_t& h, uint32_t& l) {
    __nv_bfloat162 hp = __float22bfloat162_rn(make_float2(x, y));
    float2 hf = __bfloat1622float2(hp);
    __nv_bfloat162 lp = __float22bfloat162_rn(make_float2(x - hf.x, y - hf.y));
    h = bf2u(hp); l = bf2u(lp);
}

// ================= device scratch =================
// A-operand hi/lo bf16 chunk images: [kc][n(NP)][PS]
__device__ __align__(16) __nv_bfloat16 g_Thi[(size_t)16 * NP * PS];
__device__ __align__(16) __nv_bfloat16 g_Tlo[(size_t)16 * NP * PS];
__device__ __align__(16) __nv_bfloat16 g_Xhi[(size_t)4 * NP * PS];
__device__ __align__(16) __nv_bfloat16 g_Xlo[(size_t)4 * NP * PS];
// B-operand hi/lo bf16 chunk images: [kc(20)][n(128)][PS]
__device__ __align__(16) __nv_bfloat16 g_WbHi[20 * 128 * PS];
__device__ __align__(16) __nv_bfloat16 g_WbLo[20 * 128 * PS];

__device__ float g_cnt[Nn * Rr];
__device__ float g_xr[(size_t)Nn * Hh];
__device__ float g_bias[Hh];
__device__ float g_stat[2 * Hh];
__device__ float g_bnA[Hh], g_bnB[Hh];
__device__ int g_off[Nn + 1];
__device__ int g_cur[Nn];
__device__ int g_epk[Ee];
__device__ int g_bsum[64];

// ================= zero helpers =================
__global__ void k_zero_cnt() {
    int i = blockIdx.x * blockDim.x + threadIdx.x;
    if (i < Nn * Rr) g_cnt[i] = 0.f;
}
__global__ void k_zero_stat() {
    int i = threadIdx.x;
    if (i < 2 * Hh) g_stat[i] = 0.f;
}

// ================= counts =================
__global__ void k_count(const int* __restrict__ ei, const int* __restrict__ et) {
    int e = blockIdx.x * blockDim.x + threadIdx.x;
    if (e < Ee) {
        int d = ei[Ee + e];
        int r = et[e];
        atomicAdd(&g_cnt[d * Rr + r], 1.0f);
    }
}

// ================= CSR build =================
__global__ void __launch_bounds__(256) k_scan1() {
    __shared__ int sh[256];
    int tid = threadIdx.x;
    int base = blockIdx.x * 1024;
    int d[4];
    int local = 0;
#pragma unroll
    for (int j = 0; j < 4; j++) {
        int n = base + tid * 4 + j;
        int deg = 0;
        if (n < Nn) {
#pragma unroll
            for (int r = 0; r < Rr; r++) deg += (int)g_cnt[n * Rr + r];
        }
        d[j] = deg;
        local += deg;
    }
    sh[tid] = local;
    __syncthreads();
    for (int s = 1; s < 256; s <<= 1) {
        int v = (tid >= s) ? sh[tid - s] : 0;
        __syncthreads();
        sh[tid] += v;
        __syncthreads();
    }
    int run = sh[tid] - local;
    if (tid == 255) g_bsum[blockIdx.x] = sh[255];
#pragma unroll
    for (int j = 0; j < 4; j++) {
        int n = base + tid * 4 + j;
        if (n < Nn) g_off[n] = run;
        run += d[j];
    }
}

__global__ void k_scan2() {
    __shared__ int sh[64];
    int tid = threadIdx.x;
    int v = (tid < 49) ? g_bsum[tid] : 0;
    sh[tid] = v;
    __syncthreads();
    for (int s = 1; s < 64; s <<= 1) {
        int u = (tid >= s) ? sh[tid - s] : 0;
        __syncthreads();
        sh[tid] += u;
        __syncthreads();
    }
    if (tid < 49) g_bsum[tid] = sh[tid] - v;
    if (tid == 0) g_off[Nn] = Ee;
}

__global__ void k_scan3() {
    int n = blockIdx.x * blockDim.x + threadIdx.x;
    if (n < Nn) {
        int o = g_off[n] + g_bsum[n >> 10];
        g_off[n] = o;
        g_cur[n] = o;
    }
}

__global__ void k_place(const int* __restrict__ ei, const int* __restrict__ et) {
    int e = blockIdx.x * blockDim.x + threadIdx.x;
    if (e < Ee) {
        int d = ei[Ee + e];
        int s = ei[e];
        int r = et[e];
        int pos = atomicAdd(&g_cur[d], 1);
        g_epk[pos] = s | (r << 24);
    }
}

// ================= gather-aggregate (f32x2) -> hi/lo bf16 T images =================
template <bool FROM_XR>
__global__ void __launch_bounds__(64) k_agg(const float* __restrict__ X,
                                            const float* __restrict__ comp) {
    int n = blockIdx.x;
    int c2 = threadIdx.x;            // channel pair (2c2, 2c2+1)
    __shared__ u64 coefp[Rr * 4];
    __shared__ int se[32];
    if (c2 < Rr * Bb) {
        int r = c2 >> 2, b = c2 & 3;
        float cc = g_cnt[n * Rr + r];
        coefp[c2] = pack2(comp[r * Bb + b] / fmaxf(cc, 1.0f));
    }
    int start = g_off[n], end = g_off[n + 1];
    __syncthreads();
    const float* Xp = FROM_XR ? g_xr : X;
    u64 a0 = 0, a1 = 0, a2 = 0, a3 = 0;
    for (int base = start; base < end; base += 32) {
        int m = min(32, end - base);
        if (c2 < m) se[c2] = g_epk[base + c2];
        __syncthreads();
        int i = 0;
        for (; i + 1 < m; i += 2) {
            int pk0 = se[i], pk1 = se[i + 1];
            u64 xv0 = *(const u64*)(Xp + (size_t)(pk0 & 0xFFFFFF) * Hh + 2 * c2);
            u64 xv1 = *(const u64*)(Xp + (size_t)(pk1 & 0xFFFFFF) * Hh + 2 * c2);
            int q0 = (pk0 >> 24) << 2, q1 = (pk1 >> 24) << 2;
            a0 = fma2(coefp[q0 + 0], xv0, a0);
            a1 = fma2(coefp[q0 + 1], xv0, a1);
            a2 = fma2(coefp[q0 + 2], xv0, a2);
            a3 = fma2(coefp[q0 + 3], xv0, a3);
            a0 = fma2(coefp[q1 + 0], xv1, a0);
            a1 = fma2(coefp[q1 + 1], xv1, a1);
            a2 = fma2(coefp[q1 + 2], xv1, a2);
            a3 = fma2(coefp[q1 + 3], xv1, a3);
        }
        if (i < m) {
            int pk = se[i];
            u64 xv = *(const u64*)(Xp + (size_t)(pk & 0xFFFFFF) * Hh + 2 * c2);
            int q = (pk >> 24) << 2;
            a0 = fma2(coefp[q + 0], xv, a0);
            a1 = fma2(coefp[q + 1], xv, a1);
            a2 = fma2(coefp[q + 2], xv, a2);
            a3 = fma2(coefp[q + 3], xv, a3);
        }
        __syncthreads();
    }
    // write hi/lo bf16 into chunk images: basis b -> k = b*128 + {2c2,2c2+1}
    u64 acc[4] = {a0, a1, a2, a3};
    int c = (2 * c2) & 31;
    int ksub = c2 >> 4;              // which 32-chunk within the basis' 128
#pragma unroll
    for (int b = 0; b < 4; b++) {
        uint32_t h, l;
        split_pair(lo2(acc[b]), hi2(acc[b]), h, l);
        size_t idx = ((size_t)(b * 4 + ksub) * NP + n) * PS + c;
        *(uint32_t*)&g_Thi[idx] = h;
        *(uint32_t*)&g_Tlo[idx] = l;
    }
}

// ================= x -> hi/lo images (layer-1 root/skip section) =================
__global__ void k_cvtX(const float* __restrict__ X) {
    int i = blockIdx.x * blockDim.x + threadIdx.x;
    if (i >= Nn * 64) return;
    int n = i >> 6, c2 = i & 63;
    int kc = c2 >> 4, c = (2 * c2) & 31;
    float2 v = *(const float2*)&X[(size_t)n * 128 + kc * 32 + c];
    uint32_t h, l;
    split_pair(v.x, v.y, h, l);
    size_t idx = ((size_t)kc * NP + n) * PS + c;
    *(uint32_t*)&g_Xhi[idx] = h;
    *(uint32_t*)&g_Xlo[idx] = l;
}

// ================= weight prep: hi/lo bf16 chunk images =================
__global__ void k_prepW(const float* __restrict__ bases, const float* __restrict__ root,
                        const float* __restrict__ skw, const float* __restrict__ bias,
                        const float* __restrict__ skb) {
    int e = blockIdx.x * blockDim.x + threadIdx.x;
    if (e < 128) g_bias[e] = bias[e] + skb[e];
    if (e >= 20 * 128 * 32) return;
    int kc = e >> 12;
    int rem = e & 4095;
    int n = rem >> 5;
    int c = rem & 31;
    int k = kc * 32 + c;
    float w = (k < 512) ? bases[(size_t)k * 128 + n]
                        : root[(size_t)(k - 512) * 128 + n] + skw[(size_t)(k - 512) * 128 + n];
    __nv_bfloat16 hi = __float2bfloat16(w);
    float lo = w - __bfloat162float(hi);
    int idx = kc * (128 * PS) + n * PS + c;
    g_WbHi[idx] = hi;
    g_WbLo[idx] = __float2bfloat16(lo);
}

// ================= pipelined HMMA GEMM =================
// C[M,128] = A @ W + bias; A images = T (kc 0..15) then X (kc 16..19).
// 512 threads = 16 warps (4x4), warp tile 32x32; double-buffered cp.async staging.
#define IMG_B 10240                 // 128 rows * 80B
#define STG_B (4 * IMG_B)           // Ahi,Alo,Bhi,Blo
#define SMEM_DYN (2 * STG_B)        // 81920

__global__ void __launch_bounds__(512)
k_hmma(float* __restrict__ C) {
    extern __shared__ __align__(16) uint8_t sm[];
    uint32_t smb = s2u(sm);

    int t = threadIdx.x;
    int lane = t & 31, w = t >> 5;
    int wm = w >> 2, wn = w & 3;
    int m0 = blockIdx.x * 128;

    // ldmatrix lane offsets (proven R12 geometry; 80B row stride)
    int arow = wm * 32 + (lane & 15);
    int akb  = (lane >> 4) * 16;
    int brow = wn * 32 + (lane & 7) + ((lane >> 4) << 3);
    int bkb  = ((lane >> 3) & 1) * 16;
    uint32_t aHiB[2], aLoB[2], bHiB[2], bLoB[2];
#pragma unroll
    for (int s = 0; s < 2; s++) {
        uint32_t b = smb + s * STG_B;
        aHiB[s] = b + arow * 80 + akb;
        aLoB[s] = b + IMG_B + arow * 80 + akb;
        bHiB[s] = b + 2 * IMG_B + brow * 80 + bkb;
        bLoB[s] = b + 3 * IMG_B + brow * 80 + bkb;
    }

    auto stage = [&](int kc, int s) {
        uint32_t dst = smb + s * STG_B;
        size_t arb = (kc < 16) ? ((size_t)kc * NP + m0) * 80
                               : ((size_t)(kc - 16) * NP + m0) * 80;
        const char* Ah = ((kc < 16) ? (const char*)g_Thi : (const char*)g_Xhi) + arb;
        const char* Al = ((kc < 16) ? (const char*)g_Tlo : (const char*)g_Xlo) + arb;
        const char* Bh = (const char*)g_WbHi + (size_t)kc * IMG_B;
        const char* Bl = (const char*)g_WbLo + (size_t)kc * IMG_B;
        int o = t * 16;
        cpa16(dst + o,             Ah + o);
        cpa16(dst + IMG_B + o,     Al + o);
        cpa16(dst + 2 * IMG_B + o, Bh + o);
        cpa16(dst + 3 * IMG_B + o, Bl + o);
        if (t < 128) {
            int o2 = 8192 + t * 16;
            cpa16(dst + o2,             Ah + o2);
            cpa16(dst + IMG_B + o2,     Al + o2);
            cpa16(dst + 2 * IMG_B + o2, Bh + o2);
            cpa16(dst + 3 * IMG_B + o2, Bl + o2);
        }
    };

    float cc[2][4][4];
#pragma unroll
    for (int i = 0; i < 2; i++)
#pragma unroll
        for (int j = 0; j < 4; j++)
#pragma unroll
            for (int k = 0; k < 4; k++) cc[i][j][k] = 0.f;

    stage(0, 0);
    asm volatile("cp.async.commit_group;");

    for (int kc = 0; kc < 20; kc++) {
        int cur = kc & 1;
        if (kc < 19) {
            stage(kc + 1, cur ^ 1);
            asm volatile("cp.async.commit_group;");
            asm volatile("cp.async.wait_group 1;");
        } else {
            asm volatile("cp.async.wait_group 0;");
        }
        __syncthreads();

#pragma unroll
        for (int s2 = 0; s2 < 2; s2++) {
            uint32_t kb = s2 * 32;
            uint32_t ah[2][4], al[2][4], bh[2][4], bl[2][4];
#pragma unroll
            for (int mt = 0; mt < 2; mt++) {
                ldsm4(ah[mt], aHiB[cur] + mt * (16 * 80) + kb);
                ldsm4(al[mt], aLoB[cur] + mt * (16 * 80) + kb);
            }
#pragma unroll
            for (int p = 0; p < 2; p++) {
                ldsm4(bh[p], bHiB[cur] + p * (16 * 80) + kb);
                ldsm4(bl[p], bLoB[cur] + p * (16 * 80) + kb);
            }
#pragma unroll
            for (int mt = 0; mt < 2; mt++) {
#pragma unroll
                for (int p = 0; p < 2; p++) {
                    mma16816(cc[mt][p * 2], ah[mt], &bh[p][0]);
                    mma16816(cc[mt][p * 2], ah[mt], &bl[p][0]);
                    mma16816(cc[mt][p * 2], al[mt], &bh[p][0]);
                    mma16816(cc[mt][p * 2 + 1], ah[mt], &bh[p][2]);
                    mma16816(cc[mt][p * 2 + 1], ah[mt], &bl[p][2]);
                    mma16816(cc[mt][p * 2 + 1], al[mt], &bh[p][2]);
                }
            }
        }
        __syncthreads();
    }

    // ---- epilogue ----
#pragma unroll
    for (int mt = 0; mt < 2; mt++) {
#pragma unroll
        for (int nt = 0; nt < 4; nt++) {
            int mrow = m0 + wm * 32 + mt * 16 + (lane >> 2);
            int ncol = wn * 32 + nt * 8 + (lane & 3) * 2;
            float2 bv = *(const float2*)&g_bias[ncol];
            if (mrow < Nn)
                *(float2*)&C[(size_t)mrow * 128 + ncol] =
                    make_float2(cc[mt][nt][0] + bv.x, cc[mt][nt][1] + bv.y);
            if (mrow + 8 < Nn)
                *(float2*)&C[(size_t)(mrow + 8) * 128 + ncol] =
                    make_float2(cc[mt][nt][2] + bv.x, cc[mt][nt][3] + bv.y);
        }
    }
}

// ================= BatchNorm =================
#define BN_ROWS 32
__global__ void k_bnstats(const float* __restrict__ X) {
    int c = threadIdx.x;
    int n0 = blockIdx.x * BN_ROWS;
    float s = 0.f, s2 = 0.f;
#pragma unroll 4
    for (int i = 0; i < BN_ROWS; i++) {
        int n = n0 + i;
        if (n < Nn) {
            float v = X[(size_t)n * Hh + c];
            s += v;
            s2 += v * v;
        }
    }
    atomicAdd(&g_stat[c], s);
    atomicAdd(&g_stat[Hh + c], s2);
}

__global__ void k_bnfin(const float* __restrict__ gamma, const float* __restrict__ beta) {
    int c = threadIdx.x;
    float m = g_stat[c] * (1.0f / Nn);
    float var = g_stat[Hh + c] * (1.0f / Nn) - m * m;
    float a = gamma[c] * rsqrtf(var + 1e-5f);
    g_bnA[c] = a;
    g_bnB[c] = beta[c] - m * a;
}

// BN apply + ReLU; writes fp32 xr (for gather) AND hi/lo X images (for GEMM)
__global__ void k_bnapply(const float* __restrict__ X) {
    size_t i = (size_t)blockIdx.x * blockDim.x + threadIdx.x;
    if (i >= (size_t)Nn * 32) return;
    int q = (int)(i & 31);
    int n = (int)(i >> 5);
    int cq = q * 4;
    float4 v = ((const float4*)X)[i];
    float4 a = *(const float4*)&g_bnA[cq];
    float4 b = *(const float4*)&g_bnB[cq];
    v.x = fmaxf(a.x * v.x + b.x, 0.f);
    v.y = fmaxf(a.y * v.y + b.y, 0.f);
    v.z = fmaxf(a.z * v.z + b.z, 0.f);
    v.w = fmaxf(a.w * v.w + b.w, 0.f);
    ((float4*)g_xr)[i] = v;
    uint32_t h0, l0, h1, l1;
    split_pair(v.x, v.y, h0, l0);
    split_pair(v.z, v.w, h1, l1);
    int kc = q >> 3, c = (q & 7) * 4;
    size_t idx = ((size_t)kc * NP + n) * PS + c;
    *(uint2*)&g_Xhi[idx] = make_uint2(h0, h1);
    *(uint2*)&g_Xlo[idx] = make_uint2(l0, l1);
}

extern "C" void kernel_launch(void* const* d_in, const int* in_sizes, int n_in,
                              void* d_out, int out_size) {
    const float* x       = (const float*)d_in[0];
    const int*   ei      = (const int*)d_in[1];
    const int*   et      = (const int*)d_in[2];
    const float* comp1   = (const float*)d_in[3];
    const float* bases1  = (const float*)d_in[4];
    const float* root1   = (const float*)d_in[5];
    const float* bias1   = (const float*)d_in[6];
    const float* skip1_w = (const float*)d_in[7];
    const float* skip1_b = (const float*)d_in[8];
    const float* gamma   = (const float*)d_in[9];
    const float* beta    = (const float*)d_in[10];
    const float* comp2   = (const float*)d_in[11];
    const float* bases2  = (const float*)d_in[12];
    const float* root2   = (const float*)d_in[13];
    const float* bias2   = (const float*)d_in[14];
    const float* skip2_w = (const float*)d_in[15];
    const float* skip2_b = (const float*)d_in[16];

    float* out_h  = (float*)d_out;
    float* out_x2 = (float*)d_out + (size_t)Nn * Hh;

    (void)cudaFuncSetAttribute(k_hmma, cudaFuncAttributeMaxDynamicSharedMemorySize, SMEM_DYN);

    const int MTILES = (Nn + 127) / 128;

    // ---- CSR build ----
    k_zero_cnt<<<(Nn * Rr + 255) / 256, 256>>>();
    k_count<<<(Ee + 255) / 256, 256>>>(ei, et);
    k_scan1<<<(Nn + 1023) / 1024, 256>>>();
    k_scan2<<<1, 64>>>();
    k_scan3<<<(Nn + 255) / 256, 256>>>();
    k_place<<<(Ee + 255) / 256, 256>>>(ei, et);

    // ---- layer 1 ----
    k_prepW<<<(20 * 128 * 32 + 255) / 256, 256>>>(bases1, root1, skip1_w, bias1, skip1_b);
    k_cvtX<<<(Nn * 64 + 255) / 256, 256>>>(x);
    k_agg<false><<<Nn, 64>>>(x, comp1);
    k_hmma<<<MTILES, 512, SMEM_DYN>>>(out_h);

    // ---- BatchNorm + ReLU (also emits X images for layer 2) ----
    k_zero_stat<<<1, 256>>>();
    k_bnstats<<<(Nn + BN_ROWS - 1) / BN_ROWS, 128>>>(out_h);
    k_bnfin<<<1, 128>>>(gamma, beta);
    k_bnapply<<<(unsigned)(((size_t)Nn * 32 + 255) / 256), 256>>>(out_h);

    // ---- layer 2 ----
    k_prepW<<<(20 * 128 * 32 + 255) / 256, 256>>>(bases2, root2, skip2_w, bias2, skip2_b);
    k_agg<true><<<Nn, 64>>>(nullptr, comp2);
    k_hmma<<<MTILES, 512, SMEM_DYN>>>(out_x2);
}